// round 9
// baseline (speedup 1.0000x reference)
#include <cuda_runtime.h>
#include <cuda_fp16.h>
#include <cstdint>

// ===========================================================================
// One CTA per m, 448 threads = 14 warps, each warp m32 x n64.
// GEMM rows grouped by l: l-tile covers rows q=0..15 (q=1..14 <-> n=q-1).
// xs[u][j]: u = l*16 + h + 2; rows u%16 in {0,1} are shared zero pads,
// PLUS rows 224/225 (h=14 pad + garbage row of tile l=13) — row 224 feeds the
// VALID output row (l=13, n=13, tap=2), so it must be zeroed every launch.
// Warp w: u7 = w%7 -> m-tiles (2*u7, 2*u7+1); ngrp = w/7 -> cols [ngrp*64,+64).
// Epilogue (per hc): strided t4s reads, fully contiguous out stores.
// ===========================================================================

__device__ __half g_Bh[256 * 384];   // w2^T fp16: [c][kk], kk = k*128+j

__device__ __forceinline__ uint32_t smem_u32(const void* p) {
    uint32_t a;
    asm("{ .reg .u64 t; cvta.to.shared.u64 t, %1; cvt.u32.u64 %0, t; }" : "=r"(a) : "l"(p));
    return a;
}

__global__ __launch_bounds__(256) void kB(const float* __restrict__ w2) {
    int i = blockIdx.x * 256 + threadIdx.x;          // 98304 total
    if (i >= 98304) return;
    int c  = i / 384;
    int kk = i - c * 384;
    int k  = kk >> 7;
    int j  = kk & 127;
    g_Bh[i] = __float2half(w2[j * 768 + k * 256 + c]);
}

static constexpr int XS_STRIDE = 136;   // halves (272B rows; ldmatrix conflict-free)
static constexpr int BS_STRIDE = 392;   // halves
static constexpr int T4_STRIDE = 136;   // halves

static constexpr int XS_OFF = 0;                      // 226*136*2 = 61472 B
static constexpr int BS_OFF = 61472;                  // 128*392*2 = 100352 B
static constexpr int T4_OFF = 161824;                 // 224*136*2 = 60928 B
static constexpr int SMEM_BYTES = 222752;

static constexpr int NT = 448;          // threads per CTA (14 warps)

struct GemmCtx { uint32_t a_pre0, a_pre1, b_pre; };

__device__ __forceinline__ void gemm_phase(float (&d)[2][8][4], const GemmCtx& g) {
    #pragma unroll
    for (int mi = 0; mi < 2; mi++)
        #pragma unroll
        for (int i = 0; i < 8; i++)
            #pragma unroll
            for (int q = 0; q < 4; q++) d[mi][i][q] = 0.f;
    #pragma unroll 2
    for (int s = 0; s < 24; s++) {
        const int tap = s >> 3;
        const uint32_t coff = (uint32_t)(tap * (XS_STRIDE * 2) + (s & 7) * 32);
        uint32_t a0, a1, a2, a3, a4, a5, a6, a7;
        asm volatile("ldmatrix.sync.aligned.m8n8.x4.shared.b16 {%0,%1,%2,%3}, [%4];"
                     : "=r"(a0), "=r"(a1), "=r"(a2), "=r"(a3) : "r"(g.a_pre0 + coff));
        asm volatile("ldmatrix.sync.aligned.m8n8.x4.shared.b16 {%0,%1,%2,%3}, [%4];"
                     : "=r"(a4), "=r"(a5), "=r"(a6), "=r"(a7) : "r"(g.a_pre1 + coff));
        uint32_t b_addr = g.b_pre + (uint32_t)(s * 32);
        #pragma unroll
        for (int q = 0; q < 4; q++) {
            uint32_t b0, b1, b2, b3;
            asm volatile("ldmatrix.sync.aligned.m8n8.x4.shared.b16 {%0,%1,%2,%3}, [%4];"
                         : "=r"(b0), "=r"(b1), "=r"(b2), "=r"(b3) : "r"(b_addr));
            b_addr += 16u * BS_STRIDE * 2u;
            asm volatile("mma.sync.aligned.m16n8k16.row.col.f32.f16.f16.f32 "
                         "{%0,%1,%2,%3}, {%4,%5,%6,%7}, {%8,%9}, {%0,%1,%2,%3};"
                         : "+f"(d[0][2*q][0]), "+f"(d[0][2*q][1]),
                           "+f"(d[0][2*q][2]), "+f"(d[0][2*q][3])
                         : "r"(a0), "r"(a1), "r"(a2), "r"(a3), "r"(b0), "r"(b1));
            asm volatile("mma.sync.aligned.m16n8k16.row.col.f32.f16.f16.f32 "
                         "{%0,%1,%2,%3}, {%4,%5,%6,%7}, {%8,%9}, {%0,%1,%2,%3};"
                         : "+f"(d[0][2*q+1][0]), "+f"(d[0][2*q+1][1]),
                           "+f"(d[0][2*q+1][2]), "+f"(d[0][2*q+1][3])
                         : "r"(a0), "r"(a1), "r"(a2), "r"(a3), "r"(b2), "r"(b3));
            asm volatile("mma.sync.aligned.m16n8k16.row.col.f32.f16.f16.f32 "
                         "{%0,%1,%2,%3}, {%4,%5,%6,%7}, {%8,%9}, {%0,%1,%2,%3};"
                         : "+f"(d[1][2*q][0]), "+f"(d[1][2*q][1]),
                           "+f"(d[1][2*q][2]), "+f"(d[1][2*q][3])
                         : "r"(a4), "r"(a5), "r"(a6), "r"(a7), "r"(b0), "r"(b1));
            asm volatile("mma.sync.aligned.m16n8k16.row.col.f32.f16.f16.f32 "
                         "{%0,%1,%2,%3}, {%4,%5,%6,%7}, {%8,%9}, {%0,%1,%2,%3};"
                         : "+f"(d[1][2*q+1][0]), "+f"(d[1][2*q+1][1]),
                           "+f"(d[1][2*q+1][2]), "+f"(d[1][2*q+1][3])
                         : "r"(a4), "r"(a5), "r"(a6), "r"(a7), "r"(b2), "r"(b3));
        }
    }
}

__device__ __forceinline__ void t4_store(float (&d)[2][8][4], __half* t4s,
                                         int mt0, int cbase, int lane) {
    const int q0 = lane >> 2;
    const int tq = lane & 3;
    #pragma unroll
    for (int mi = 0; mi < 2; mi++) {
        const int rbase = (mt0 + mi) * 16;
        #pragma unroll
        for (int i = 0; i < 8; i++) {
            const int c0 = (cbase + i) * 8 + tq * 2;
            *(__half2*)(t4s + (rbase + q0) * T4_STRIDE + c0) =
                __floats2half2_rn(d[mi][i][0], d[mi][i][1]);
            *(__half2*)(t4s + (rbase + q0 + 8) * T4_STRIDE + c0) =
                __floats2half2_rn(d[mi][i][2], d[mi][i][3]);
        }
    }
}

__global__ __launch_bounds__(NT, 1) void kMain(const float* __restrict__ x,
                                               const float* __restrict__ w1,
                                               float* __restrict__ out) {
    extern __shared__ char smem[];
    __half* xs  = (__half*)(smem + XS_OFF);
    __half* Bs  = (__half*)(smem + BS_OFF);
    __half* t4s = (__half*)(smem + T4_OFF);

    const int tid  = threadIdx.x;
    const int m    = blockIdx.x;
    const int wid  = tid >> 5;
    const int lane = tid & 31;

    // ================= Phase A: zero pads + build xs + load Bs(0) ==========
    {   // zero rows u%16 in {0,1}: 28 pad rows PLUS rows 224,225 (r=28,29).
        // Row 224 is the h=14 pad of tile l=13 (feeds valid n=13 at tap=2) —
        // must be zeroed EVERY launch (uninit smem diverges across replays).
        uint32_t* xz = (uint32_t*)xs;
        for (int i = tid; i < 30 * 64; i += NT) {
            int r   = i >> 6;
            int row = (r >> 1) * 16 + (r & 1);
            xz[(row * XS_STRIDE) / 2 + (i & 63)] = 0;
        }
    }
    const float* xm = x + (size_t)m * 25088;
    for (int i = tid; i < 25088; i += NT) {
        int j  = i / 196;
        int lh = i - j * 196;
        int l  = lh / 14;
        int h  = lh - l * 14;
        xs[(l * 16 + h + 2) * XS_STRIDE + j] = __float2half(xm[i]);
    }
    {
        const uint32_t* src = (const uint32_t*)g_Bh;          // hc=0
        for (int i = tid; i < 128 * 192; i += NT) {
            int c  = i / 192;
            int kw = i - c * 192;
            *(uint32_t*)(Bs + c * BS_STRIDE + kw * 2) = src[i];
        }
    }

    // ---- per-warp constants: warp = (u7, ngrp); m-tiles 2*u7, 2*u7+1 ----
    const int u7   = wid % 7;
    const int ngrp = wid / 7;            // 0 or 1
    const int mt0  = u7 * 2;
    const int cbase = ngrp * 8;

    GemmCtx g;
    g.a_pre0 = smem_u32(xs) +
        (uint32_t)(((mt0 * 16 + (lane & 15)) * XS_STRIDE + ((lane >> 4) << 3)) * 2);
    g.a_pre1 = g.a_pre0 + (uint32_t)(16 * XS_STRIDE * 2);
    {
        const int n_in16 = (((lane >> 4) & 1) << 3) + (lane & 7);
        const int k_half = ((lane >> 3) & 1) << 3;
        g.b_pre = smem_u32(Bs) +
            (uint32_t)(((cbase * 8 + n_in16) * BS_STRIDE + k_half) * 2);
    }

    float* om = out + (size_t)m * 50176;
    const float2* w1v = (const float2*)w1;

    float d[2][8][4];
    __syncthreads();

    // ================= hc = 0 ==============================================
    gemm_phase(d, g);
    __syncthreads();

    // t4s store(0) + Bs(1) load
    t4_store(d, t4s, mt0, cbase, lane);
    {
        const uint32_t* src = (const uint32_t*)(g_Bh + 128 * 384);   // hc=1
        for (int i = tid; i < 128 * 192; i += NT) {
            int c  = i / 192;
            int kw = i - c * 192;
            *(uint32_t*)(Bs + c * BS_STRIDE + kw * 2) = src[i];
        }
    }
    __syncthreads();

    // epilogue(0) then gemm(1); disjoint read sets, no barrier between
    for (int i = tid; i < 25088; i += NT) {
        int cl = i / 196;
        int rr = i - cl * 196;
        int p  = rr / 14;
        int b  = rr - p * 14;
        int l1 = (p == 0) ? 13 : p - 1;
        int l2 = (p < 2) ? p + 12 : p - 2;
        float2 wv = w1v[cl];                              // hc=0
        float v = wv.x * __half2float(t4s[(l1 * 16 + 1 + b) * T4_STRIDE + cl])
                + wv.y * __half2float(t4s[(l2 * 16 + 1 + b) * T4_STRIDE + cl]);
        om[i] = v;
    }
    gemm_phase(d, g);
    __syncthreads();

    // t4s store(1)
    t4_store(d, t4s, mt0, cbase, lane);
    __syncthreads();

    // epilogue(1)
    for (int i = tid; i < 25088; i += NT) {
        int cl = i / 196;
        int rr = i - cl * 196;
        int p  = rr / 14;
        int b  = rr - p * 14;
        int l1 = (p == 0) ? 13 : p - 1;
        int l2 = (p < 2) ? p + 12 : p - 2;
        float2 wv = w1v[128 + cl];                        // hc=1
        float v = wv.x * __half2float(t4s[(l1 * 16 + 1 + b) * T4_STRIDE + cl])
                + wv.y * __half2float(t4s[(l2 * 16 + 1 + b) * T4_STRIDE + cl]);
        om[25088 + i] = v;
    }
}

// ===========================================================================
extern "C" void kernel_launch(void* const* d_in, const int* in_sizes, int n_in,
                              void* d_out, int out_size) {
    const float* x  = (const float*)d_in[0];   // (1024, 1792, 14)
    const float* w1 = (const float*)d_in[1];   // (256, 2)
    const float* w2 = (const float*)d_in[2];   // (128, 3, 256)
    float* out = (float*)d_out;                // (1024, 256, 14, 14)

    static int attr_done = 0;
    if (!attr_done) {
        cudaFuncSetAttribute(kMain, cudaFuncAttributeMaxDynamicSharedMemorySize,
                             SMEM_BYTES);
        attr_done = 1;
    }

    kB<<<384, 256>>>(w2);
    kMain<<<1024, NT, SMEM_BYTES>>>(x, w1, out);
}